// round 1
// baseline (speedup 1.0000x reference)
#include <cuda_runtime.h>

// LSTM_53815940218945: B=8192, T=256, I=1, H=50, O=1
// One block = 4 batch elements. 224 threads:
//   threads 0..199: gate rows (PyTorch order i,f,g,o), W_hh row in registers
//   threads 0..49 : also own cell k (c in registers), do pointwise update
// Inner product uses packed fma.rn.f32x2 (2 batch lanes per FMA).

#define B_TILE 4
#define T_LEN  256
#define H      50
#define HP     52      // H padded to multiple of 4
#define G4     200     // 4*H gate rows

typedef unsigned long long u64;

__device__ __forceinline__ u64 pack2(float a, float b) {
    u64 r; asm("mov.b64 %0, {%1, %2};" : "=l"(r) : "f"(a), "f"(b)); return r;
}
__device__ __forceinline__ u64 fma2(u64 a, u64 b, u64 c) {
    u64 d; asm("fma.rn.f32x2 %0, %1, %2, %3;" : "=l"(d) : "l"(a), "l"(b), "l"(c));
    return d;
}
__device__ __forceinline__ float rcp_fast(float x) {
    float y; asm("rcp.approx.f32 %0, %1;" : "=f"(y) : "f"(x)); return y;
}
__device__ __forceinline__ float ex2f(float x) {
    float y; asm("ex2.approx.f32 %0, %1;" : "=f"(y) : "f"(x)); return y;
}
// sigmoid(x) = 1/(1+exp(-x)),  exp(-x) = ex2(-x*log2(e))
__device__ __forceinline__ float sigmoidf_(float x) {
    return rcp_fast(1.0f + ex2f(-1.4426950408889634f * x));
}
// tanh(x) = 2/(1+exp(-2x)) - 1,  exp(-2x) = ex2(-x*2*log2(e))
__device__ __forceinline__ float tanh_fast(float x) {
    return fmaf(2.0f, rcp_fast(1.0f + ex2f(-2.8853900817779268f * x)), -1.0f);
}

__global__ void __launch_bounds__(224, 3) lstm_kernel(
    const float* __restrict__ x,      // [B, T, 1]
    const float* __restrict__ W_ih,   // [200, 1]
    const float* __restrict__ W_hh,   // [200, 50]
    const float* __restrict__ b_ih,   // [200]
    const float* __restrict__ b_hh,   // [200]
    const float* __restrict__ W_lin,  // [1, 50]
    const float* __restrict__ b_lin,  // [1]
    float* __restrict__ out)          // [B]
{
    __shared__ __align__(16) float x_s[T_LEN * B_TILE];   // [t][b]
    __shared__ __align__(16) float h_s[HP * B_TILE];      // [k][b]
    __shared__ __align__(16) float gates_s[G4 * B_TILE];  // [j][b]

    const int j  = threadIdx.x;
    const int b0 = blockIdx.x * B_TILE;

    // Preload x tile: x_s[t][b] = x[(b0+b)*T + t]  (coalesced global reads)
    for (int i = j; i < T_LEN * B_TILE; i += blockDim.x) {
        int b = i >> 8;          // i / 256
        int t = i & (T_LEN - 1); // i % 256
        x_s[t * B_TILE + b] = x[(b0 + b) * T_LEN + t];
    }
    // h0 = 0 (including padded rows 50,51 which stay 0 forever)
    for (int i = j; i < HP * B_TILE; i += blockDim.x) h_s[i] = 0.0f;

    // Per-thread weight row in registers
    float W[HP];
    u64 wih2 = 0ull, bias2 = 0ull;
    if (j < G4) {
        #pragma unroll
        for (int k = 0; k < HP; k++) W[k] = (k < H) ? W_hh[j * H + k] : 0.0f;
        float wih  = W_ih[j];
        float bias = b_ih[j] + b_hh[j];
        wih2  = pack2(wih, wih);
        bias2 = pack2(bias, bias);
    }
    // Cell state in registers for update threads (j < 50)
    float c0 = 0.0f, c1 = 0.0f, c2 = 0.0f, c3 = 0.0f;

    __syncthreads();

    for (int t = 0; t < T_LEN; t++) {
        // ---- gate phase: gates[j][b] = bias + wih*x[b][t] + sum_k W[k]*h[k][b]
        if (j < G4) {
            ulonglong2 xv = *reinterpret_cast<const ulonglong2*>(&x_s[t * B_TILE]);
            u64 acc01 = fma2(wih2, xv.x, bias2);
            u64 acc23 = fma2(wih2, xv.y, bias2);
            #pragma unroll
            for (int k = 0; k < HP; k++) {
                ulonglong2 hv = *reinterpret_cast<const ulonglong2*>(&h_s[k * B_TILE]);
                u64 w2 = pack2(W[k], W[k]);
                acc01 = fma2(w2, hv.x, acc01);
                acc23 = fma2(w2, hv.y, acc23);
            }
            ulonglong2 g; g.x = acc01; g.y = acc23;
            *reinterpret_cast<ulonglong2*>(&gates_s[j * B_TILE]) = g;
        }
        __syncthreads();

        // ---- update phase: c = f*c + i*g ; h = o*tanh(c)
        if (j < H) {
            float4 gi = *reinterpret_cast<const float4*>(&gates_s[(0 * H + j) * B_TILE]);
            float4 gf = *reinterpret_cast<const float4*>(&gates_s[(1 * H + j) * B_TILE]);
            float4 gg = *reinterpret_cast<const float4*>(&gates_s[(2 * H + j) * B_TILE]);
            float4 go = *reinterpret_cast<const float4*>(&gates_s[(3 * H + j) * B_TILE]);
            float4 hn;
            {
                float i_ = sigmoidf_(gi.x), f_ = sigmoidf_(gf.x);
                float g_ = tanh_fast(gg.x), o_ = sigmoidf_(go.x);
                c0 = fmaf(f_, c0, i_ * g_);
                hn.x = o_ * tanh_fast(c0);
            }
            {
                float i_ = sigmoidf_(gi.y), f_ = sigmoidf_(gf.y);
                float g_ = tanh_fast(gg.y), o_ = sigmoidf_(go.y);
                c1 = fmaf(f_, c1, i_ * g_);
                hn.y = o_ * tanh_fast(c1);
            }
            {
                float i_ = sigmoidf_(gi.z), f_ = sigmoidf_(gf.z);
                float g_ = tanh_fast(gg.z), o_ = sigmoidf_(go.z);
                c2 = fmaf(f_, c2, i_ * g_);
                hn.z = o_ * tanh_fast(c2);
            }
            {
                float i_ = sigmoidf_(gi.w), f_ = sigmoidf_(gf.w);
                float g_ = tanh_fast(gg.w), o_ = sigmoidf_(go.w);
                c3 = fmaf(f_, c3, i_ * g_);
                hn.w = o_ * tanh_fast(c3);
            }
            *reinterpret_cast<float4*>(&h_s[j * B_TILE]) = hn;
        }
        __syncthreads();
    }

    // ---- final linear: out[b] = b_lin + sum_k h[k][b] * W_lin[k]
    if (j < B_TILE) {
        float s = b_lin[0];
        #pragma unroll
        for (int k = 0; k < H; k++)
            s = fmaf(h_s[k * B_TILE + j], W_lin[k], s);
        out[b0 + j] = s;
    }
}

extern "C" void kernel_launch(void* const* d_in, const int* in_sizes, int n_in,
                              void* d_out, int out_size) {
    const float* x     = (const float*)d_in[0];
    const float* W_ih  = (const float*)d_in[1];
    const float* W_hh  = (const float*)d_in[2];
    const float* b_ih  = (const float*)d_in[3];
    const float* b_hh  = (const float*)d_in[4];
    const float* W_lin = (const float*)d_in[5];
    const float* b_lin = (const float*)d_in[6];
    float* out = (float*)d_out;

    int B = in_sizes[0] / T_LEN;     // I = 1
    int blocks = B / B_TILE;         // 2048 for B=8192

    lstm_kernel<<<blocks, 224>>>(x, W_ih, W_hh, b_ih, b_hh, W_lin, b_lin, out);
}

// round 2
// speedup vs baseline: 1.0557x; 1.0557x over previous
#include <cuda_runtime.h>

// LSTM_53815940218945: B=8192, T=256, I=1, H=50, O=1
// One block = 4 batch elements, 224 threads (7 warps).
//   threads 0..199: gate rows (PyTorch order i,f,g,o), W_hh row PRE-PACKED
//                   as 52 u64 (w,w) pairs in registers.
//   threads 0..199: update phase, 1 cell-lane each (k=j/4, lane=j%4),
//                   cell state c in a single register.
// Inner product uses packed fma.rn.f32x2 (2 batch lanes per FMA), no per-step
// repacking.

#define B_TILE 4
#define T_LEN  256
#define H      50
#define HP     52      // H padded to multiple of 4
#define G4     200     // 4*H gate rows

typedef unsigned long long u64;

__device__ __forceinline__ u64 pack2(float a, float b) {
    u64 r; asm("mov.b64 %0, {%1, %2};" : "=l"(r) : "f"(a), "f"(b)); return r;
}
__device__ __forceinline__ u64 fma2(u64 a, u64 b, u64 c) {
    u64 d; asm("fma.rn.f32x2 %0, %1, %2, %3;" : "=l"(d) : "l"(a), "l"(b), "l"(c));
    return d;
}
__device__ __forceinline__ float rcp_fast(float x) {
    float y; asm("rcp.approx.f32 %0, %1;" : "=f"(y) : "f"(x)); return y;
}
__device__ __forceinline__ float ex2f(float x) {
    float y; asm("ex2.approx.f32 %0, %1;" : "=f"(y) : "f"(x)); return y;
}
// sigmoid(x) = 1/(1+exp(-x)),  exp(-x) = ex2(-x*log2(e))
__device__ __forceinline__ float sigmoidf_(float x) {
    return rcp_fast(1.0f + ex2f(-1.4426950408889634f * x));
}
// tanh(x) = 2/(1+exp(-2x)) - 1
__device__ __forceinline__ float tanh_fast(float x) {
    return fmaf(2.0f, rcp_fast(1.0f + ex2f(-2.8853900817779268f * x)), -1.0f);
}

__global__ void __launch_bounds__(224, 2) lstm_kernel(
    const float* __restrict__ x,      // [B, T, 1]
    const float* __restrict__ W_ih,   // [200, 1]
    const float* __restrict__ W_hh,   // [200, 50]
    const float* __restrict__ b_ih,   // [200]
    const float* __restrict__ b_hh,   // [200]
    const float* __restrict__ W_lin,  // [1, 50]
    const float* __restrict__ b_lin,  // [1]
    float* __restrict__ out)          // [B]
{
    __shared__ __align__(16) float x_s[T_LEN * B_TILE];   // [t][b]
    __shared__ __align__(16) float h_s[HP * B_TILE];      // [k][b]
    __shared__ __align__(16) float gates_s[G4 * B_TILE];  // [j][b]

    const int j  = threadIdx.x;
    const int b0 = blockIdx.x * B_TILE;

    // Preload x tile: x_s[t][b] = x[(b0+b)*T + t]
    for (int i = j; i < T_LEN * B_TILE; i += blockDim.x) {
        int b = i >> 8;          // i / 256
        int t = i & (T_LEN - 1); // i % 256
        x_s[t * B_TILE + b] = x[(b0 + b) * T_LEN + t];
    }
    // h0 = 0 (padded rows 50,51 stay 0 forever)
    for (int i = j; i < HP * B_TILE; i += blockDim.x) h_s[i] = 0.0f;

    // Per-thread weight row, PRE-PACKED as (w,w) u64 pairs — never repacked.
    u64 W2[HP];
    u64 wih2 = 0ull, bias2 = 0ull;
    if (j < G4) {
        #pragma unroll
        for (int k = 0; k < HP; k++) {
            float w = (k < H) ? W_hh[j * H + k] : 0.0f;
            W2[k] = pack2(w, w);
        }
        float wih  = W_ih[j];
        float bias = b_ih[j] + b_hh[j];
        wih2  = pack2(wih, wih);
        bias2 = pack2(bias, bias);
    }

    // Update-phase ownership: thread j<200 owns cell k=j/4, batch lane j%4.
    // Single cell-state register.
    float c_reg = 0.0f;

    __syncthreads();

    for (int t = 0; t < T_LEN; t++) {
        // ---- gate phase: gates[j][b] = bias + wih*x[b][t] + sum_k W[k]*h[k][b]
        if (j < G4) {
            ulonglong2 xv = *reinterpret_cast<const ulonglong2*>(&x_s[t * B_TILE]);
            u64 acc01 = fma2(wih2, xv.x, bias2);
            u64 acc23 = fma2(wih2, xv.y, bias2);

            // 2-deep prefetch of h rows (broadcast LDS.128)
            ulonglong2 hv = *reinterpret_cast<const ulonglong2*>(&h_s[0]);
            #pragma unroll
            for (int k = 0; k < HP; k++) {
                ulonglong2 hn;
                if (k + 1 < HP)
                    hn = *reinterpret_cast<const ulonglong2*>(&h_s[(k + 1) * B_TILE]);
                acc01 = fma2(W2[k], hv.x, acc01);
                acc23 = fma2(W2[k], hv.y, acc23);
                if (k + 1 < HP) hv = hn;
            }
            ulonglong2 g; g.x = acc01; g.y = acc23;
            *reinterpret_cast<ulonglong2*>(&gates_s[j * B_TILE]) = g;
        }
        __syncthreads();

        // ---- update phase: one (cell, lane) per thread, spread over 200 threads
        if (j < G4) {
            // gates_s[(q*H + k)*4 + lane] = gates_s[q*200 + j] : conflict-free
            float gi = gates_s[0 * G4 + j];
            float gf = gates_s[1 * G4 + j];
            float gg = gates_s[2 * G4 + j];
            float go = gates_s[3 * G4 + j];

            float i_ = sigmoidf_(gi);
            float f_ = sigmoidf_(gf);
            float g_ = tanh_fast(gg);
            float o_ = sigmoidf_(go);
            c_reg = fmaf(f_, c_reg, i_ * g_);
            h_s[j] = o_ * tanh_fast(c_reg);   // h_s[k*4+lane] == h_s[j]
        }
        __syncthreads();
    }

    // ---- final linear: out[b] = b_lin + sum_k h[k][b] * W_lin[k]
    if (j < B_TILE) {
        float s = b_lin[0];
        #pragma unroll
        for (int k = 0; k < H; k++)
            s = fmaf(h_s[k * B_TILE + j], W_lin[k], s);
        out[b0 + j] = s;
    }
}

extern "C" void kernel_launch(void* const* d_in, const int* in_sizes, int n_in,
                              void* d_out, int out_size) {
    const float* x     = (const float*)d_in[0];
    const float* W_ih  = (const float*)d_in[1];
    const float* W_hh  = (const float*)d_in[2];
    const float* b_ih  = (const float*)d_in[3];
    const float* b_hh  = (const float*)d_in[4];
    const float* W_lin = (const float*)d_in[5];
    const float* b_lin = (const float*)d_in[6];
    float* out = (float*)d_out;

    int B = in_sizes[0] / T_LEN;     // I = 1
    int blocks = B / B_TILE;         // 2048 for B=8192

    lstm_kernel<<<blocks, 224>>>(x, W_ih, W_hh, b_ih, b_hh, W_lin, b_lin, out);
}

// round 3
// speedup vs baseline: 1.1295x; 1.0698x over previous
#include <cuda_runtime.h>

// LSTM_53815940218945: B=8192, T=256, I=1, H=50, O=1
// One block = 4 batch elements, 224 threads (7 warps).
// h stored in two SMEM planes so one 16B LDS yields TWO k-steps of packed
// fma.rn.f32x2 operands:
//   plane01[k] = (h[k][b0], h[k][b1])   (u64)
//   plane23[k] = (h[k][b2], h[k][b3])   (u64)
// Gate phase per thread-step: 26 LDS.128 + 104 FFMA2 (4 indep acc chains).
// Update phase: 200 threads, one (cell,lane) each, c in a register,
// activations via HW tanh.approx (5 MUFU/thread).

#define B_TILE 4
#define T_LEN  256
#define H      50
#define HP     52      // H padded to multiple of 4
#define G4     200     // 4*H gate rows

typedef unsigned long long u64;

__device__ __forceinline__ u64 pack2(float a, float b) {
    u64 r; asm("mov.b64 %0, {%1, %2};" : "=l"(r) : "f"(a), "f"(b)); return r;
}
__device__ __forceinline__ u64 fma2(u64 a, u64 b, u64 c) {
    u64 d; asm("fma.rn.f32x2 %0, %1, %2, %3;" : "=l"(d) : "l"(a), "l"(b), "l"(c));
    return d;
}
__device__ __forceinline__ u64 add2(u64 a, u64 b) {
    u64 d; asm("add.rn.f32x2 %0, %1, %2;" : "=l"(d) : "l"(a), "l"(b));
    return d;
}
__device__ __forceinline__ float tanh_hw(float x) {
    float y; asm("tanh.approx.f32 %0, %1;" : "=f"(y) : "f"(x)); return y;
}
__device__ __forceinline__ float sigmoid_hw(float x) {
    return fmaf(0.5f, tanh_hw(0.5f * x), 0.5f);
}

__global__ void __launch_bounds__(224, 2) lstm_kernel(
    const float* __restrict__ x,      // [B, T, 1]
    const float* __restrict__ W_ih,   // [200, 1]
    const float* __restrict__ W_hh,   // [200, 50]
    const float* __restrict__ b_ih,   // [200]
    const float* __restrict__ b_hh,   // [200]
    const float* __restrict__ W_lin,  // [1, 50]
    const float* __restrict__ b_lin,  // [1]
    float* __restrict__ out)          // [B]
{
    __shared__ __align__(16) float x_s[T_LEN * B_TILE];   // [t][b]
    __shared__ __align__(16) u64 h01_s[HP];               // (h[k][0], h[k][1])
    __shared__ __align__(16) u64 h23_s[HP];               // (h[k][2], h[k][3])
    __shared__ __align__(16) float gates_s[G4 * B_TILE];  // [row][b]

    const int j  = threadIdx.x;
    const int b0 = blockIdx.x * B_TILE;

    // Preload x tile: x_s[t][b] = x[(b0+b)*T + t]
    for (int i = j; i < T_LEN * B_TILE; i += blockDim.x) {
        int b = i >> 8;
        int t = i & (T_LEN - 1);
        x_s[t * B_TILE + b] = x[(b0 + b) * T_LEN + t];
    }
    // h0 = 0 (padded rows 50,51 stay 0 forever)
    if (j < HP) { h01_s[j] = 0ull; h23_s[j] = 0ull; }

    // Per-thread weight row, pre-packed as (w,w) u64 pairs.
    u64 W2[HP];
    u64 wih2 = 0ull, bias2 = 0ull;
    if (j < G4) {
        #pragma unroll
        for (int k = 0; k < HP; k++) {
            float w = (k < H) ? W_hh[j * H + k] : 0.0f;
            W2[k] = pack2(w, w);
        }
        float wih  = W_ih[j];
        float bias = b_ih[j] + b_hh[j];
        wih2  = pack2(wih, wih);
        bias2 = pack2(bias, bias);
    }

    // Update phase: thread j<200 owns cell k=j>>2, batch lane j&3.
    float c_reg = 0.0f;
    const int u_k    = j >> 2;
    const int u_lane = j & 3;
    // Target float slot inside the planes for writing h back:
    float* h_f = (u_lane < 2) ? (float*)h01_s : (float*)h23_s;
    const int h_idx = u_k * 2 + (u_lane & 1);

    __syncthreads();

    for (int t = 0; t < T_LEN; t++) {
        // ---- gate phase ----
        if (j < G4) {
            ulonglong2 xv = *reinterpret_cast<const ulonglong2*>(&x_s[t * B_TILE]);
            u64 a01a = fma2(wih2, xv.x, bias2);
            u64 a23a = fma2(wih2, xv.y, bias2);
            u64 a01b = 0ull;   // (0.0f, 0.0f)
            u64 a23b = 0ull;

            #pragma unroll
            for (int k = 0; k < HP; k += 4) {
                ulonglong2 hA01 = *reinterpret_cast<const ulonglong2*>(&h01_s[k]);
                ulonglong2 hA23 = *reinterpret_cast<const ulonglong2*>(&h23_s[k]);
                ulonglong2 hB01 = *reinterpret_cast<const ulonglong2*>(&h01_s[k + 2]);
                ulonglong2 hB23 = *reinterpret_cast<const ulonglong2*>(&h23_s[k + 2]);
                a01a = fma2(W2[k],     hA01.x, a01a);
                a23a = fma2(W2[k],     hA23.x, a23a);
                a01a = fma2(W2[k + 1], hA01.y, a01a);
                a23a = fma2(W2[k + 1], hA23.y, a23a);
                a01b = fma2(W2[k + 2], hB01.x, a01b);
                a23b = fma2(W2[k + 2], hB23.x, a23b);
                a01b = fma2(W2[k + 3], hB01.y, a01b);
                a23b = fma2(W2[k + 3], hB23.y, a23b);
            }
            ulonglong2 g;
            g.x = add2(a01a, a01b);
            g.y = add2(a23a, a23b);
            *reinterpret_cast<ulonglong2*>(&gates_s[j * B_TILE]) = g;
        }
        __syncthreads();

        // ---- update phase: one (cell, lane) per thread ----
        if (j < G4) {
            float gi = gates_s[0 * G4 + j];
            float gf = gates_s[1 * G4 + j];
            float gg = gates_s[2 * G4 + j];
            float go = gates_s[3 * G4 + j];

            float i_ = sigmoid_hw(gi);
            float f_ = sigmoid_hw(gf);
            float g_ = tanh_hw(gg);
            float o_ = sigmoid_hw(go);
            c_reg = fmaf(f_, c_reg, i_ * g_);
            h_f[h_idx] = o_ * tanh_hw(c_reg);
        }
        __syncthreads();
    }

    // ---- final linear: out[b] = b_lin + sum_k h[k][b] * W_lin[k]
    if (j < B_TILE) {
        const float* hp = (j < 2) ? (const float*)h01_s : (const float*)h23_s;
        const int off = j & 1;
        float s = b_lin[0];
        #pragma unroll
        for (int k = 0; k < H; k++)
            s = fmaf(hp[k * 2 + off], W_lin[k], s);
        out[b0 + j] = s;
    }
}

extern "C" void kernel_launch(void* const* d_in, const int* in_sizes, int n_in,
                              void* d_out, int out_size) {
    const float* x     = (const float*)d_in[0];
    const float* W_ih  = (const float*)d_in[1];
    const float* W_hh  = (const float*)d_in[2];
    const float* b_ih  = (const float*)d_in[3];
    const float* b_hh  = (const float*)d_in[4];
    const float* W_lin = (const float*)d_in[5];
    const float* b_lin = (const float*)d_in[6];
    float* out = (float*)d_out;

    int B = in_sizes[0] / T_LEN;     // I = 1
    int blocks = B / B_TILE;         // 2048 for B=8192

    lstm_kernel<<<blocks, 224>>>(x, W_ih, W_hh, b_ih, b_hh, W_lin, b_lin, out);
}

// round 4
// speedup vs baseline: 1.2442x; 1.1016x over previous
#include <cuda_runtime.h>

// LSTM_53815940218945: B=8192, T=256, I=1, H=50, O=1
// Block = 4 batch lanes, 224 threads = 7 full warps.
// Thread (q,s): q=j>>2 (cell, 0..55; 50..55 dummy), s=j&3 (k-split).
// Owns gate rows {q, 50+q, 100+q, 150+q} = (i,f,g,o) of cell q over
// k in [13s, 13s+13). One 16B LDS.128 of h[k][0..3] feeds 8 FFMA2.
// Partial gate sums reduced across the 4 split lanes via shfl.bfly (xor 1,2);
// then thread s does the pointwise update for (cell q, lane s).
// h double-buffered in SMEM -> ONE barrier per step.

#define T_LEN  256
#define H      50
#define KCH    13     // k's per split (4*13 = 52 = H padded)
#define QPAD   56     // padded cells; QPAD*4 = 224 threads

typedef unsigned long long u64;

__device__ __forceinline__ u64 pack2(float a, float b) {
    u64 r; asm("mov.b64 %0, {%1, %2};" : "=l"(r) : "f"(a), "f"(b)); return r;
}
__device__ __forceinline__ u64 fma2(u64 a, u64 b, u64 c) {
    u64 d; asm("fma.rn.f32x2 %0, %1, %2, %3;" : "=l"(d) : "l"(a), "l"(b), "l"(c));
    return d;
}
__device__ __forceinline__ u64 add2(u64 a, u64 b) {
    u64 d; asm("add.rn.f32x2 %0, %1, %2;" : "=l"(d) : "l"(a), "l"(b));
    return d;
}
__device__ __forceinline__ float tanh_hw(float x) {
    float y; asm("tanh.approx.f32 %0, %1;" : "=f"(y) : "f"(x)); return y;
}
__device__ __forceinline__ float sigmoid_hw(float x) {
    return fmaf(0.5f, tanh_hw(0.5f * x), 0.5f);
}

__global__ void __launch_bounds__(224, 2) lstm_kernel(
    const float* __restrict__ x,      // [B, T, 1]
    const float* __restrict__ W_ih,   // [200, 1]
    const float* __restrict__ W_hh,   // [200, 50]
    const float* __restrict__ b_ih,   // [200]
    const float* __restrict__ b_hh,   // [200]
    const float* __restrict__ W_lin,  // [1, 50]
    const float* __restrict__ b_lin,  // [1]
    float* __restrict__ out)          // [B]
{
    __shared__ __align__(16) float x_s[T_LEN * 4];       // [t][lane]
    __shared__ __align__(16) float h2_s[2][QPAD * 4];    // [plane][k][lane]

    const int j = threadIdx.x;
    const int q = j >> 2;     // cell
    const int s = j & 3;      // k-split / batch lane for update
    const int b0 = blockIdx.x * 4;
    const int k0 = s * KCH;

    // Preload x tile: x_s[t][b] = x[(b0+b)*T + t]
    for (int i = j; i < T_LEN * 4; i += 224) {
        int b = i >> 8;
        int t = i & (T_LEN - 1);
        x_s[t * 4 + b] = x[(b0 + b) * T_LEN + t];
    }
    h2_s[0][j] = 0.0f;
    h2_s[1][j] = 0.0f;

    // Weights: 4 rows x 13 k, packed (w,w). Dummy cells (q>=50) get zeros.
    u64 W2[4][KCH];
    float bias[4], wih[4];
    const bool act = (q < H);
    #pragma unroll
    for (int r = 0; r < 4; r++) {
        int row = r * H + q;  // PyTorch gate order i,f,g,o
        bias[r] = act ? (b_ih[row] + b_hh[row]) : 0.0f;
        wih[r]  = act ? W_ih[row] : 0.0f;
        #pragma unroll
        for (int i = 0; i < KCH; i++) {
            int k = k0 + i;
            float w = (act && k < H) ? W_hh[row * H + k] : 0.0f;
            W2[r][i] = pack2(w, w);
        }
    }
    float c_reg = 0.0f;

    __syncthreads();

    #pragma unroll 1
    for (int t = 0; t < T_LEN; t++) {
        const int ping = t & 1;
        const ulonglong2* hp =
            reinterpret_cast<const ulonglong2*>(&h2_s[ping][k0 * 4]);

        // ---- gate partials: 13 LDS.128, 104 FFMA2 ----
        u64 a[4][2];
        #pragma unroll
        for (int r = 0; r < 4; r++) { a[r][0] = 0ull; a[r][1] = 0ull; }
        #pragma unroll
        for (int i = 0; i < KCH; i++) {
            ulonglong2 hv = hp[i];
            #pragma unroll
            for (int r = 0; r < 4; r++) {
                a[r][0] = fma2(W2[r][i], hv.x, a[r][0]);
                a[r][1] = fma2(W2[r][i], hv.y, a[r][1]);
            }
        }

        // ---- butterfly reduce over the 4 split lanes (xor 1, 2) ----
        #pragma unroll
        for (int m = 1; m <= 2; m <<= 1) {
            #pragma unroll
            for (int r = 0; r < 4; r++) {
                a[r][0] = add2(a[r][0], __shfl_xor_sync(0xffffffffu, a[r][0], m));
                a[r][1] = add2(a[r][1], __shfl_xor_sync(0xffffffffu, a[r][1], m));
            }
        }

        // ---- extract lane s, add bias + wih*x, pointwise update ----
        float g4[4];
        #pragma unroll
        for (int r = 0; r < 4; r++) {
            u64 v = (s < 2) ? a[r][0] : a[r][1];
            float lo = __uint_as_float((unsigned)v);
            float hi = __uint_as_float((unsigned)(v >> 32));
            g4[r] = (s & 1) ? hi : lo;
        }
        float xv = x_s[t * 4 + s];
        float gi = fmaf(wih[0], xv, g4[0] + bias[0]);
        float gf = fmaf(wih[1], xv, g4[1] + bias[1]);
        float gg = fmaf(wih[2], xv, g4[2] + bias[2]);
        float go = fmaf(wih[3], xv, g4[3] + bias[3]);

        float i_ = sigmoid_hw(gi);
        float f_ = sigmoid_hw(gf);
        float g_ = tanh_hw(gg);
        float o_ = sigmoid_hw(go);
        c_reg = fmaf(f_, c_reg, i_ * g_);
        float hn = o_ * tanh_hw(c_reg);

        // write to the OTHER plane; one barrier per step
        h2_s[ping ^ 1][q * 4 + s] = hn;
        __syncthreads();
    }

    // Final h is in plane 0 (T_LEN even). out[b] = b_lin + sum_k h[k][b]*W_lin[k]
    if (j < 4) {
        const float* hf = h2_s[0];
        float sum = b_lin[0];
        #pragma unroll
        for (int k = 0; k < H; k++)
            sum = fmaf(hf[k * 4 + j], W_lin[k], sum);
        out[b0 + j] = sum;
    }
}

extern "C" void kernel_launch(void* const* d_in, const int* in_sizes, int n_in,
                              void* d_out, int out_size) {
    const float* x     = (const float*)d_in[0];
    const float* W_ih  = (const float*)d_in[1];
    const float* W_hh  = (const float*)d_in[2];
    const float* b_ih  = (const float*)d_in[3];
    const float* b_hh  = (const float*)d_in[4];
    const float* W_lin = (const float*)d_in[5];
    const float* b_lin = (const float*)d_in[6];
    float* out = (float*)d_out;

    int B = in_sizes[0] / T_LEN;   // I = 1
    int blocks = B / 4;            // 2048 for B=8192

    lstm_kernel<<<blocks, 224>>>(x, W_ih, W_hh, b_ih, b_hh, W_lin, b_lin, out);
}

// round 5
// speedup vs baseline: 1.3572x; 1.0908x over previous
#include <cuda_runtime.h>

// LSTM_53815940218945: B=8192, T=256, I=1, H=50, O=1
// Block = 4 batch lanes, 224 threads = 7 full warps.
// Thread (q,s): q=j>>2 (cell, 0..55; 50..55 dummy), s=j&3 (k-split).
// Owns gate rows {q, 50+q, 100+q, 150+q} = (i,f,g,o) of cell q over
// k in [13s, 13s+13). One 16B LDS.128 of h[k][0..3] feeds 8 FFMA2.
// Gate partials combined across the 4 split lanes with a 2-step
// REDUCE-SCATTER (12 SHFL.32, not a 32-SHFL butterfly): each thread ends
// with exactly its own (cell q, lane s) gates. h double-buffered -> 1
// barrier per step.

#define T_LEN  256
#define H      50
#define KCH    13     // k's per split (4*13 = 52 = H padded)
#define QPAD   56     // padded cells; QPAD*4 = 224 threads

typedef unsigned long long u64;

__device__ __forceinline__ u64 pack2(float a, float b) {
    u64 r; asm("mov.b64 %0, {%1, %2};" : "=l"(r) : "f"(a), "f"(b)); return r;
}
__device__ __forceinline__ u64 fma2(u64 a, u64 b, u64 c) {
    u64 d; asm("fma.rn.f32x2 %0, %1, %2, %3;" : "=l"(d) : "l"(a), "l"(b), "l"(c));
    return d;
}
__device__ __forceinline__ u64 add2(u64 a, u64 b) {
    u64 d; asm("add.rn.f32x2 %0, %1, %2;" : "=l"(d) : "l"(a), "l"(b));
    return d;
}
__device__ __forceinline__ float lo_of(u64 v) {
    return __uint_as_float((unsigned)v);
}
__device__ __forceinline__ float hi_of(u64 v) {
    return __uint_as_float((unsigned)(v >> 32));
}
__device__ __forceinline__ float tanh_hw(float x) {
    float y; asm("tanh.approx.f32 %0, %1;" : "=f"(y) : "f"(x)); return y;
}
__device__ __forceinline__ float sigmoid_hw(float x) {
    return fmaf(0.5f, tanh_hw(0.5f * x), 0.5f);
}

__global__ void __launch_bounds__(224, 2) lstm_kernel(
    const float* __restrict__ x,      // [B, T, 1]
    const float* __restrict__ W_ih,   // [200, 1]
    const float* __restrict__ W_hh,   // [200, 50]
    const float* __restrict__ b_ih,   // [200]
    const float* __restrict__ b_hh,   // [200]
    const float* __restrict__ W_lin,  // [1, 50]
    const float* __restrict__ b_lin,  // [1]
    float* __restrict__ out)          // [B]
{
    __shared__ __align__(16) float x_s[T_LEN * 4];       // [t][lane]
    __shared__ __align__(16) float h2_s[2][QPAD * 4];    // [plane][k][lane]

    const int j = threadIdx.x;
    const int q = j >> 2;     // cell
    const int s = j & 3;      // k-split / batch lane for update
    const int b0 = blockIdx.x * 4;
    const int k0 = s * KCH;

    // Preload x tile: x_s[t][b] = x[(b0+b)*T + t]
    for (int i = j; i < T_LEN * 4; i += 224) {
        int b = i >> 8;
        int t = i & (T_LEN - 1);
        x_s[t * 4 + b] = x[(b0 + b) * T_LEN + t];
    }
    h2_s[0][j] = 0.0f;
    h2_s[1][j] = 0.0f;

    // Weights: 4 rows x 13 k, packed (w,w). Dummy cells (q>=50) get zeros.
    u64 W2[4][KCH];
    float bias[4], wih[4];
    const bool act = (q < H);
    #pragma unroll
    for (int r = 0; r < 4; r++) {
        int row = r * H + q;  // PyTorch gate order i,f,g,o
        bias[r] = act ? (b_ih[row] + b_hh[row]) : 0.0f;
        wih[r]  = act ? W_ih[row] : 0.0f;
        #pragma unroll
        for (int i = 0; i < KCH; i++) {
            int k = k0 + i;
            float w = (act && k < H) ? W_hh[row * H + k] : 0.0f;
            W2[r][i] = pack2(w, w);
        }
    }
    float c_reg = 0.0f;
    const bool lowhalf = (s < 2);   // my lane lives in the .x (lanes 0,1) u64
    const bool oddlane = (s & 1);   // my lane is the hi float of its u64

    __syncthreads();

    #pragma unroll 1
    for (int t = 0; t < T_LEN; t++) {
        const int ping = t & 1;
        const ulonglong2* hp =
            reinterpret_cast<const ulonglong2*>(&h2_s[ping][k0 * 4]);

        // ---- gate partials: 13 LDS.128, 104 FFMA2 ----
        u64 a[4][2];
        #pragma unroll
        for (int r = 0; r < 4; r++) { a[r][0] = 0ull; a[r][1] = 0ull; }
        #pragma unroll
        for (int i = 0; i < KCH; i++) {
            ulonglong2 hv = hp[i];
            #pragma unroll
            for (int r = 0; r < 4; r++) {
                a[r][0] = fma2(W2[r][i], hv.x, a[r][0]);
                a[r][1] = fma2(W2[r][i], hv.y, a[r][1]);
            }
        }

        // ---- reduce-scatter over the 4 split lanes: 12 SHFL.32 total ----
        // Step 1 (xor 2): keep the u64 containing my lane; partner sends
        // its matching u64 (its keep_sel is the complement of mine).
        u64 keep[4];
        #pragma unroll
        for (int r = 0; r < 4; r++) {
            u64 kv = lowhalf ? a[r][0] : a[r][1];
            u64 sv = lowhalf ? a[r][1] : a[r][0];
            u64 rv = __shfl_xor_sync(0xffffffffu, sv, 2);
            keep[r] = add2(kv, rv);
        }
        // Step 2 (xor 1): exchange single floats; I keep element (s&1).
        float g4[4];
        #pragma unroll
        for (int r = 0; r < 4; r++) {
            float mine  = oddlane ? hi_of(keep[r]) : lo_of(keep[r]);
            float sendf = oddlane ? lo_of(keep[r]) : hi_of(keep[r]);
            float rf = __shfl_xor_sync(0xffffffffu, sendf, 1);
            g4[r] = mine + rf;
        }

        // ---- add bias + wih*x, pointwise update for (cell q, lane s) ----
        float xv = x_s[t * 4 + s];
        float gi = fmaf(wih[0], xv, g4[0] + bias[0]);
        float gf = fmaf(wih[1], xv, g4[1] + bias[1]);
        float gg = fmaf(wih[2], xv, g4[2] + bias[2]);
        float go = fmaf(wih[3], xv, g4[3] + bias[3]);

        float i_ = sigmoid_hw(gi);
        float f_ = sigmoid_hw(gf);
        float g_ = tanh_hw(gg);
        float o_ = sigmoid_hw(go);
        c_reg = fmaf(f_, c_reg, i_ * g_);
        float hn = o_ * tanh_hw(c_reg);

        // write to the OTHER plane; one barrier per step
        h2_s[ping ^ 1][q * 4 + s] = hn;
        __syncthreads();
    }

    // Final h is in plane 0 (T_LEN even). out[b] = b_lin + sum_k h[k][b]*W_lin[k]
    if (j < 4) {
        const float* hf = h2_s[0];
        float sum = b_lin[0];
        #pragma unroll
        for (int k = 0; k < H; k++)
            sum = fmaf(hf[k * 4 + j], W_lin[k], sum);
        out[b0 + j] = sum;
    }
}

extern "C" void kernel_launch(void* const* d_in, const int* in_sizes, int n_in,
                              void* d_out, int out_size) {
    const float* x     = (const float*)d_in[0];
    const float* W_ih  = (const float*)d_in[1];
    const float* W_hh  = (const float*)d_in[2];
    const float* b_ih  = (const float*)d_in[3];
    const float* b_hh  = (const float*)d_in[4];
    const float* W_lin = (const float*)d_in[5];
    const float* b_lin = (const float*)d_in[6];
    float* out = (float*)d_out;

    int B = in_sizes[0] / T_LEN;   // I = 1
    int blocks = B / 4;            // 2048 for B=8192

    lstm_kernel<<<blocks, 224>>>(x, W_ih, W_hh, b_ih, b_hh, W_lin, b_lin, out);
}

// round 6
// speedup vs baseline: 1.3896x; 1.0239x over previous
#include <cuda_runtime.h>

// LSTM_53815940218945: B=8192, T=256, I=1, H=50, O=1
// Block = 8 batch lanes, 200 threads (6.25 warps) -- ZERO dummy threads.
// Thread (q,s): q=j>>2 (cell 0..49), s=j&3 (k-split over KCH=13).
// Owns gate rows {q, 50+q, 100+q, 150+q} = (i,f,g,o) of cell q.
// Two lane-groups (batch lanes 0-3, 4-7) processed sequentially per step,
// reusing accumulator registers; group-B FMA overlaps group-A's MUFU chain.
// Reduce-scatter over the 4 split lanes (12 SHFL.32 per group, group masks).
// h double-buffered -> ONE barrier per step.

#define T_LEN  256
#define H      50
#define KCH    13     // k's per split (4*13 = 52 = H padded)
#define KP     52     // padded k rows in h planes
#define BT     8      // batch lanes per block

typedef unsigned long long u64;

__device__ __forceinline__ u64 pack2(float a, float b) {
    u64 r; asm("mov.b64 %0, {%1, %2};" : "=l"(r) : "f"(a), "f"(b)); return r;
}
__device__ __forceinline__ u64 fma2(u64 a, u64 b, u64 c) {
    u64 d; asm("fma.rn.f32x2 %0, %1, %2, %3;" : "=l"(d) : "l"(a), "l"(b), "l"(c));
    return d;
}
__device__ __forceinline__ u64 add2(u64 a, u64 b) {
    u64 d; asm("add.rn.f32x2 %0, %1, %2;" : "=l"(d) : "l"(a), "l"(b));
    return d;
}
__device__ __forceinline__ float lo_of(u64 v) {
    return __uint_as_float((unsigned)v);
}
__device__ __forceinline__ float hi_of(u64 v) {
    return __uint_as_float((unsigned)(v >> 32));
}
__device__ __forceinline__ float tanh_hw(float x) {
    float y; asm("tanh.approx.f32 %0, %1;" : "=f"(y) : "f"(x)); return y;
}
__device__ __forceinline__ float sigmoid_hw(float x) {
    return fmaf(0.5f, tanh_hw(0.5f * x), 0.5f);
}

__global__ void __launch_bounds__(200, 2) lstm_kernel(
    const float* __restrict__ x,      // [B, T, 1]
    const float* __restrict__ W_ih,   // [200, 1]
    const float* __restrict__ W_hh,   // [200, 50]
    const float* __restrict__ b_ih,   // [200]
    const float* __restrict__ b_hh,   // [200]
    const float* __restrict__ W_lin,  // [1, 50]
    const float* __restrict__ b_lin,  // [1]
    float* __restrict__ out)          // [B]
{
    __shared__ __align__(16) float x_s[T_LEN * BT];    // [t][lane]
    __shared__ __align__(16) float h2_s[2][KP * BT];   // [plane][k][lane]

    const int j = threadIdx.x;        // 0..199
    const int q = j >> 2;             // cell 0..49
    const int s = j & 3;              // k-split
    const int b0 = blockIdx.x * BT;
    const int k0 = s * KCH;

    // shfl group mask: the 4 lanes (split group) this thread belongs to
    const unsigned gmask = 0xFu << ((j & 31) & ~3);

    // Preload x tile: x_s[t][b] = x[(b0+b)*T + t]
    for (int i = j; i < T_LEN * BT; i += 200) {
        int b = i >> 8;
        int t = i & (T_LEN - 1);
        x_s[t * BT + b] = x[(b0 + b) * T_LEN + t];
    }
    // zero both h planes incl. pad rows 50,51 (never rewritten -> stay 0)
    for (int i = j; i < KP * BT; i += 200) {
        h2_s[0][i] = 0.0f;
        h2_s[1][i] = 0.0f;
    }

    // Weights: 4 gate rows x KCH ks, packed (w,w).
    u64 W2[4][KCH];
    float bias[4], wih[4];
    #pragma unroll
    for (int r = 0; r < 4; r++) {
        int row = r * H + q;  // PyTorch gate order i,f,g,o
        bias[r] = b_ih[row] + b_hh[row];
        wih[r]  = W_ih[row];
        #pragma unroll
        for (int i = 0; i < KCH; i++) {
            int k = k0 + i;
            float w = (k < H) ? W_hh[row * H + k] : 0.0f;
            W2[r][i] = pack2(w, w);
        }
    }
    float c_reg[2] = {0.0f, 0.0f};
    const bool lowhalf = (s < 2);
    const bool oddlane = (s & 1);

    __syncthreads();

    #pragma unroll 1
    for (int t = 0; t < T_LEN; t++) {
        const int ping = t & 1;
        const float* hplane = h2_s[ping];
        float* hnext = h2_s[ping ^ 1];

        #pragma unroll
        for (int g = 0; g < 2; g++) {
            // ---- gate partials for lanes [g*4, g*4+4): 13 LDS.128, 104 FFMA2
            u64 a[4][2];
            #pragma unroll
            for (int r = 0; r < 4; r++) { a[r][0] = 0ull; a[r][1] = 0ull; }
            #pragma unroll
            for (int i = 0; i < KCH; i++) {
                ulonglong2 hv = *reinterpret_cast<const ulonglong2*>(
                    &hplane[(k0 + i) * BT + g * 4]);
                #pragma unroll
                for (int r = 0; r < 4; r++) {
                    a[r][0] = fma2(W2[r][i], hv.x, a[r][0]);
                    a[r][1] = fma2(W2[r][i], hv.y, a[r][1]);
                }
            }

            // ---- reduce-scatter over the 4 split lanes (12 SHFL.32) ----
            u64 keep[4];
            #pragma unroll
            for (int r = 0; r < 4; r++) {
                u64 kv = lowhalf ? a[r][0] : a[r][1];
                u64 sv = lowhalf ? a[r][1] : a[r][0];
                u64 rv = __shfl_xor_sync(gmask, sv, 2);
                keep[r] = add2(kv, rv);
            }
            float g4[4];
            #pragma unroll
            for (int r = 0; r < 4; r++) {
                float mine  = oddlane ? hi_of(keep[r]) : lo_of(keep[r]);
                float sendf = oddlane ? lo_of(keep[r]) : hi_of(keep[r]);
                float rf = __shfl_xor_sync(gmask, sendf, 1);
                g4[r] = mine + rf;
            }

            // ---- pointwise update for (cell q, batch lane g*4+s) ----
            float xv = x_s[t * BT + g * 4 + s];
            float gi = fmaf(wih[0], xv, g4[0] + bias[0]);
            float gf = fmaf(wih[1], xv, g4[1] + bias[1]);
            float gg = fmaf(wih[2], xv, g4[2] + bias[2]);
            float go = fmaf(wih[3], xv, g4[3] + bias[3]);

            float i_ = sigmoid_hw(gi);
            float f_ = sigmoid_hw(gf);
            float g_ = tanh_hw(gg);
            float o_ = sigmoid_hw(go);
            c_reg[g] = fmaf(f_, c_reg[g], i_ * g_);
            float hn = o_ * tanh_hw(c_reg[g]);

            hnext[q * BT + g * 4 + s] = hn;
        }
        __syncthreads();
    }

    // Final h is in plane 0 (T_LEN even). out[b] = b_lin + sum_k h[k][b]*W_lin[k]
    if (j < BT) {
        const float* hf = h2_s[0];
        float sum = b_lin[0];
        #pragma unroll
        for (int k = 0; k < H; k++)
            sum = fmaf(hf[k * BT + j], W_lin[k], sum);
        out[b0 + j] = sum;
    }
}

extern "C" void kernel_launch(void* const* d_in, const int* in_sizes, int n_in,
                              void* d_out, int out_size) {
    const float* x     = (const float*)d_in[0];
    const float* W_ih  = (const float*)d_in[1];
    const float* W_hh  = (const float*)d_in[2];
    const float* b_ih  = (const float*)d_in[3];
    const float* b_hh  = (const float*)d_in[4];
    const float* W_lin = (const float*)d_in[5];
    const float* b_lin = (const float*)d_in[6];
    float* out = (float*)d_out;

    int B = in_sizes[0] / T_LEN;   // I = 1
    int blocks = B / BT;           // 1024 for B=8192

    lstm_kernel<<<blocks, 200>>>(x, W_ih, W_hh, b_ih, b_hh, W_lin, b_lin, out);
}